// round 4
// baseline (speedup 1.0000x reference)
#include <cuda_runtime.h>
#include <cstdint>
#include <cstddef>

#define N_NODES 100000
#define NHID    128
#define E_EDGES 1600000
#define NB      ((N_NODES + 1023) / 1024)   // 98 scan blocks

// -------- scratch (allocation-free: __device__ globals) --------
__device__ int   g_deg[N_NODES];      // source-degree (incl. self loop)
__device__ int   g_indeg[N_NODES];    // target in-degree (excl. self loop)
__device__ float g_dis[N_NODES];      // rsqrt(deg)
__device__ int   g_start[N_NODES];    // CSR row starts (targets)
__device__ int   g_fill[N_NODES];     // fill cursors
__device__ int   g_csr[E_EDGES];      // CSR: source node per in-edge
__device__ int   g_spine[NB];         // scan spine
__device__ float g_y[(size_t)N_NODES * NHID];   // x = f @ W^T + b (unscaled)
__device__ float g_wt[NHID * NHID];   // W transposed: wt[k][c] = W[c][k]

__device__ __forceinline__ uint32_t f2tf32(float v) {
    uint32_t r;
    asm("cvt.rna.tf32.f32 %0, %1;" : "=r"(r) : "f"(v));
    return r;
}

// -------- W transpose (ordinal 0) --------
__global__ void k_transpose_w(const float* __restrict__ W) {
    int idx = blockIdx.x * blockDim.x + threadIdx.x;   // 16384 threads exactly
    int k = idx >> 7, c = idx & 127;
    g_wt[idx] = W[c * 128 + k];
}

// -------- degree init (self loop => 1) + indeg zero (ordinal 1) --------
__global__ void k_init() {
    int i = blockIdx.x * blockDim.x + threadIdx.x;
    if (i < N_NODES) { g_deg[i] = 1; g_indeg[i] = 0; }
}

// -------- count source degree + target in-degree (ordinal 2) --------
__global__ void k_count(const int* __restrict__ row, const int* __restrict__ col) {
    int e = blockIdx.x * blockDim.x + threadIdx.x;   // exact grid: E/256 blocks
    atomicAdd(&g_deg[row[e]], 1);
    atomicAdd(&g_indeg[col[e]], 1);
}

// -------- GEMM via 3xTF32 mma.sync (ordinal 3 -> profiled) --------
// Block tile 128x128, 8 warps, warp tile 32 rows x 64 cols
// (2 m-tiles of m16 x 8 n-tiles of n8), K chunked by 16 (2 k-steps of 8).
__global__ __launch_bounds__(256) void k_gemm(const float* __restrict__ f,
                                              const float* __restrict__ bias) {
    __shared__ float fsh_hi[128][20];   // stride 20: (20*g+tg)%32 is a permutation
    __shared__ float fsh_lo[128][20];
    __shared__ float wsh_hi[16][136];   // stride 136: (8*k+n)%32 is a permutation
    __shared__ float wsh_lo[16][136];

    const int tid  = threadIdx.x;
    const int warp = tid >> 5, lane = tid & 31;
    const int g    = lane >> 2, tg = lane & 3;
    const int wr   = (warp >> 1) * 32;    // warp row base within block
    const int wc   = (warp & 1) * 64;     // warp col base within block
    const int r0   = blockIdx.x * 128;

    // accumulators initialized with bias (c0,c1 row g; c2,c3 row g+8 -> same cols)
    float acc[2][8][4];
#pragma unroll
    for (int nt = 0; nt < 8; nt++) {
        float2 bv = __ldg((const float2*)(bias + wc + nt * 8) + tg);
#pragma unroll
        for (int mt = 0; mt < 2; mt++) {
            acc[mt][nt][0] = bv.x; acc[mt][nt][1] = bv.y;
            acc[mt][nt][2] = bv.x; acc[mt][nt][3] = bv.y;
        }
    }

    for (int kc = 0; kc < 8; kc++) {
        const int k0 = kc * 16;
        // stage W chunk [16][128] with hi/lo split
#pragma unroll
        for (int i = tid; i < 2048; i += 256) {
            int kk = i >> 7, n = i & 127;
            float v  = g_wt[(k0 + kk) * 128 + n];
            float hi = __uint_as_float(f2tf32(v));
            wsh_hi[kk][n] = hi;
            wsh_lo[kk][n] = __uint_as_float(f2tf32(v - hi));
        }
        // stage f chunk [128][16] with hi/lo split
#pragma unroll
        for (int i = tid; i < 2048; i += 256) {
            int r = i >> 4, kk = i & 15;
            int gr = r0 + r;
            float v  = (gr < N_NODES) ? f[(size_t)gr * 128 + k0 + kk] : 0.0f;
            float hi = __uint_as_float(f2tf32(v));
            fsh_hi[r][kk] = hi;
            fsh_lo[r][kk] = __uint_as_float(f2tf32(v - hi));
        }
        __syncthreads();

#pragma unroll
        for (int ks = 0; ks < 2; ks++) {
            const int kb = ks * 8;
            // A fragments (2 m-tiles, hi+lo): conflict-free LDS
            uint32_t ah[2][4], al[2][4];
#pragma unroll
            for (int mt = 0; mt < 2; mt++) {
                int rA = wr + mt * 16 + g;
                ah[mt][0] = __float_as_uint(fsh_hi[rA][kb + tg]);
                ah[mt][1] = __float_as_uint(fsh_hi[rA + 8][kb + tg]);
                ah[mt][2] = __float_as_uint(fsh_hi[rA][kb + tg + 4]);
                ah[mt][3] = __float_as_uint(fsh_hi[rA + 8][kb + tg + 4]);
                al[mt][0] = __float_as_uint(fsh_lo[rA][kb + tg]);
                al[mt][1] = __float_as_uint(fsh_lo[rA + 8][kb + tg]);
                al[mt][2] = __float_as_uint(fsh_lo[rA][kb + tg + 4]);
                al[mt][3] = __float_as_uint(fsh_lo[rA + 8][kb + tg + 4]);
            }
            // B fragments (8 n-tiles, hi+lo)
            uint32_t bh[8][2], bl[8][2];
#pragma unroll
            for (int nt = 0; nt < 8; nt++) {
                int nB = wc + nt * 8 + g;
                bh[nt][0] = __float_as_uint(wsh_hi[kb + tg][nB]);
                bh[nt][1] = __float_as_uint(wsh_hi[kb + tg + 4][nB]);
                bl[nt][0] = __float_as_uint(wsh_lo[kb + tg][nB]);
                bl[nt][1] = __float_as_uint(wsh_lo[kb + tg + 4][nB]);
            }
            // 3xTF32: small terms first, then hi*hi
#pragma unroll
            for (int mt = 0; mt < 2; mt++) {
#pragma unroll
                for (int nt = 0; nt < 8; nt++) {
                    float* d = acc[mt][nt];
#define MMA(A, B)                                                              \
    asm volatile(                                                              \
        "mma.sync.aligned.m16n8k8.row.col.f32.tf32.tf32.f32 "                  \
        "{%0,%1,%2,%3}, {%4,%5,%6,%7}, {%8,%9}, {%0,%1,%2,%3};"                \
        : "+f"(d[0]), "+f"(d[1]), "+f"(d[2]), "+f"(d[3])                       \
        : "r"((A)[0]), "r"((A)[1]), "r"((A)[2]), "r"((A)[3]),                  \
          "r"((B)[0]), "r"((B)[1]))
                    MMA(al[mt], bh[nt]);
                    MMA(ah[mt], bl[nt]);
                    MMA(ah[mt], bh[nt]);
#undef MMA
                }
            }
        }
        __syncthreads();
    }

    // epilogue: write y (float2 per accumulator row)
#pragma unroll
    for (int mt = 0; mt < 2; mt++) {
        int rowA = r0 + wr + mt * 16 + g;
        int rowB = rowA + 8;
#pragma unroll
        for (int nt = 0; nt < 8; nt++) {
            int colv = wc + nt * 8 + tg * 2;
            if (rowA < N_NODES)
                *(float2*)(g_y + (size_t)rowA * 128 + colv) =
                    make_float2(acc[mt][nt][0], acc[mt][nt][1]);
            if (rowB < N_NODES)
                *(float2*)(g_y + (size_t)rowB * 128 + colv) =
                    make_float2(acc[mt][nt][2], acc[mt][nt][3]);
        }
    }
}

// -------- dis = rsqrt(deg) (ordinal 4) --------
__global__ void k_rsqrt() {
    int i = blockIdx.x * blockDim.x + threadIdx.x;
    if (i < N_NODES) g_dis[i] = rsqrtf((float)g_deg[i]);
}

// -------- scan stage 1: per-block sums (ordinal 5) --------
__global__ __launch_bounds__(1024) void k_scan_block() {
    __shared__ int sh[1024];
    int i = blockIdx.x * 1024 + threadIdx.x;
    sh[threadIdx.x] = (i < N_NODES) ? g_indeg[i] : 0;
    __syncthreads();
#pragma unroll
    for (int off = 512; off > 0; off >>= 1) {
        if (threadIdx.x < off) sh[threadIdx.x] += sh[threadIdx.x + off];
        __syncthreads();
    }
    if (threadIdx.x == 0) g_spine[blockIdx.x] = sh[0];
}

// -------- scan stage 2: exclusive scan of spine (ordinal 6, tiny) --------
__global__ void k_scan_spine() {
    int acc = 0;
    for (int b = 0; b < NB; b++) { int v = g_spine[b]; g_spine[b] = acc; acc += v; }
}

// -------- scan stage 3: block-local exclusive scan + spine offset (ordinal 7) ----
__global__ __launch_bounds__(1024) void k_scan_final() {
    __shared__ int sh[1024];
    int i = blockIdx.x * 1024 + threadIdx.x;
    int v = (i < N_NODES) ? g_indeg[i] : 0;
    sh[threadIdx.x] = v;
    __syncthreads();
    for (int off = 1; off < 1024; off <<= 1) {
        int t = (threadIdx.x >= off) ? sh[threadIdx.x - off] : 0;
        __syncthreads();
        sh[threadIdx.x] += t;
        __syncthreads();
    }
    if (i < N_NODES) {
        int excl = sh[threadIdx.x] - v + g_spine[blockIdx.x];
        g_start[i] = excl;
        g_fill[i]  = excl;
    }
}

// -------- CSR fill (ordinal 8) --------
__global__ void k_fill(const int* __restrict__ row, const int* __restrict__ col) {
    int e = blockIdx.x * blockDim.x + threadIdx.x;   // exact grid: E/256
    int pos = atomicAdd(&g_fill[col[e]], 1);
    g_csr[pos] = row[e];
}

// -------- aggregate: out[c] = dis_c*(dis_c*x_c + sum_r dis_r*x_r) (ordinal 9) ----
__global__ __launch_bounds__(256) void k_agg(float* __restrict__ out) {
    const int warp = (blockIdx.x * 256 + threadIdx.x) >> 5;   // node id, exact grid
    const int lane = threadIdx.x & 31;
    const float4* yy = (const float4*)g_y;

    const int c = warp;
    const float dc = g_dis[c];
    float4 acc = __ldg(yy + (size_t)c * 32 + lane);
    acc.x *= dc; acc.y *= dc; acc.z *= dc; acc.w *= dc;   // self-loop: dis_c * x_c

    const int s = g_start[c];
    const int n = g_indeg[c];
    for (int k = 0; k < n; k++) {
        int src = __ldg(&g_csr[s + k]);                   // uniform across warp
        float dr = __ldg(&g_dis[src]);
        float4 v = __ldg(yy + (size_t)src * 32 + lane);
        acc.x += dr * v.x; acc.y += dr * v.y;
        acc.z += dr * v.z; acc.w += dr * v.w;
    }
    acc.x *= dc; acc.y *= dc; acc.z *= dc; acc.w *= dc;
    ((float4*)out)[(size_t)c * 32 + lane] = acc;
}

extern "C" void kernel_launch(void* const* d_in, const int* in_sizes, int n_in,
                              void* d_out, int out_size) {
    const float* f     = (const float*)d_in[0];
    const int*   edges = (const int*)d_in[1];   // (2, E) int32
    const float* W     = (const float*)d_in[2];
    const float* b     = (const float*)d_in[3];
    float*       out   = (float*)d_out;

    const int* row = edges;             // edges[0] = sources
    const int* col = edges + E_EDGES;   // edges[1] = targets

    k_transpose_w<<<64, 256>>>(W);                         // 0
    k_init<<<(N_NODES + 255) / 256, 256>>>();              // 1
    k_count<<<E_EDGES / 256, 256>>>(row, col);             // 2
    k_gemm<<<(N_NODES + 127) / 128, 256>>>(f, b);          // 3  <- profiled slot
    k_rsqrt<<<(N_NODES + 255) / 256, 256>>>();             // 4
    k_scan_block<<<NB, 1024>>>();                          // 5
    k_scan_spine<<<1, 1>>>();                              // 6
    k_scan_final<<<NB, 1024>>>();                          // 7
    k_fill<<<E_EDGES / 256, 256>>>(row, col);              // 8
    k_agg<<<N_NODES / 8, 256>>>(out);                      // 9
}

// round 5
// speedup vs baseline: 1.2217x; 1.2217x over previous
#include <cuda_runtime.h>
#include <cstdint>
#include <cstddef>

#define N_NODES 100000
#define NHID    128
#define E_EDGES 1600000
#define NB      ((N_NODES + 1023) / 1024)   // 98 scan blocks

// -------- scratch (allocation-free: __device__ globals) --------
__device__ int   g_deg[N_NODES];
__device__ int   g_indeg[N_NODES];
__device__ float g_dis[N_NODES];
__device__ int   g_start[N_NODES];
__device__ int   g_fill[N_NODES];
__device__ int   g_csr[E_EDGES];
__device__ int   g_spine[NB];
__device__ float g_y[(size_t)N_NODES * NHID];   // x = f @ W^T + b (unscaled)
__device__ float g_wt[NHID * NHID];             // wt[k][c] = W[c][k]

__device__ __forceinline__ uint32_t f2tf32(float v) {
    uint32_t r;
    asm("cvt.rna.tf32.f32 %0, %1;" : "=r"(r) : "f"(v));
    return r;
}
__device__ __forceinline__ uint32_t smem_u32(const void* p) {
    uint32_t a;
    asm("{ .reg .u64 t; cvta.to.shared.u64 t, %1; cvt.u32.u64 %0, t; }"
        : "=r"(a) : "l"(p));
    return a;
}

// -------- W transpose (ordinal 0) --------
__global__ void k_transpose_w(const float* __restrict__ W) {
    int idx = blockIdx.x * blockDim.x + threadIdx.x;   // 16384 threads exactly
    int k = idx >> 7, c = idx & 127;
    g_wt[idx] = W[c * 128 + k];
}

// -------- degree init (ordinal 1) --------
__global__ void k_init() {
    int i = blockIdx.x * blockDim.x + threadIdx.x;
    if (i < N_NODES) { g_deg[i] = 1; g_indeg[i] = 0; }
}

// -------- count degrees (ordinal 2) --------
__global__ void k_count(const int* __restrict__ row, const int* __restrict__ col) {
    int e = blockIdx.x * blockDim.x + threadIdx.x;   // exact grid
    atomicAdd(&g_deg[row[e]], 1);
    atomicAdd(&g_indeg[col[e]], 1);
}

// -------- GEMM via 3xTF32 mma, cp.async double-buffered (ordinal 3) --------
// 128 threads, block tile 64x128, warp tile 32x64, raw smem + split-at-load.
__global__ __launch_bounds__(128, 3) void k_gemm(const float* __restrict__ f,
                                                 const float* __restrict__ bias) {
    __shared__ __align__(16) float fsh[2][64][20];    // raw f chunk, stride 20
    __shared__ __align__(16) float wsh[2][16][136];   // raw W chunk, stride 136

    const int tid  = threadIdx.x;
    const int warp = tid >> 5, lane = tid & 31;
    const int g    = lane >> 2, tg = lane & 3;
    const int wr   = (warp >> 1) * 32;
    const int wc   = (warp & 1) * 64;
    const int r0   = blockIdx.x * 64;

    float acc[2][8][4];
#pragma unroll
    for (int nt = 0; nt < 8; nt++) {
        float2 bv = __ldg((const float2*)(bias + wc + nt * 8) + tg);
#pragma unroll
        for (int mt = 0; mt < 2; mt++) {
            acc[mt][nt][0] = bv.x; acc[mt][nt][1] = bv.y;
            acc[mt][nt][2] = bv.x; acc[mt][nt][3] = bv.y;
        }
    }

    auto stage = [&](int buf, int k0) {
        // f chunk: 64 rows x 16 floats = 256 x 16B; clamp OOB rows (discarded)
#pragma unroll
        for (int j = 0; j < 2; j++) {
            int u = tid + 128 * j;
            int r = u >> 2, q = u & 3;
            int gr = r0 + r; if (gr >= N_NODES) gr = N_NODES - 1;
            uint32_t dst = smem_u32(&fsh[buf][r][q * 4]);
            const float* src = f + (size_t)gr * 128 + k0 + q * 4;
            asm volatile("cp.async.ca.shared.global [%0], [%1], 16;"
                         :: "r"(dst), "l"(src));
        }
        // W chunk: 16 rows x 128 floats = 512 x 16B
#pragma unroll
        for (int j = 0; j < 4; j++) {
            int u = tid + 128 * j;
            int kk = u >> 5, q = u & 31;
            uint32_t dst = smem_u32(&wsh[buf][kk][q * 4]);
            const float* src = g_wt + (size_t)(k0 + kk) * 128 + q * 4;
            asm volatile("cp.async.ca.shared.global [%0], [%1], 16;"
                         :: "r"(dst), "l"(src));
        }
    };

    stage(0, 0);
    asm volatile("cp.async.commit_group;");

    for (int kc = 0; kc < 8; kc++) {
        asm volatile("cp.async.wait_group 0;");
        __syncthreads();
        if (kc + 1 < 8) {
            stage((kc + 1) & 1, (kc + 1) * 16);
            asm volatile("cp.async.commit_group;");
        }
        const int buf = kc & 1;

#pragma unroll
        for (int ks = 0; ks < 2; ks++) {
            const int kb = ks * 8;
            uint32_t ah[2][4], al[2][4];
#pragma unroll
            for (int mt = 0; mt < 2; mt++) {
                int rA = wr + mt * 16 + g;
                float v0 = fsh[buf][rA][kb + tg];
                float v1 = fsh[buf][rA + 8][kb + tg];
                float v2 = fsh[buf][rA][kb + tg + 4];
                float v3 = fsh[buf][rA + 8][kb + tg + 4];
                ah[mt][0] = f2tf32(v0); al[mt][0] = f2tf32(v0 - __uint_as_float(ah[mt][0]));
                ah[mt][1] = f2tf32(v1); al[mt][1] = f2tf32(v1 - __uint_as_float(ah[mt][1]));
                ah[mt][2] = f2tf32(v2); al[mt][2] = f2tf32(v2 - __uint_as_float(ah[mt][2]));
                ah[mt][3] = f2tf32(v3); al[mt][3] = f2tf32(v3 - __uint_as_float(ah[mt][3]));
            }
            uint32_t bh[8][2], bl[8][2];
#pragma unroll
            for (int nt = 0; nt < 8; nt++) {
                int nB = wc + nt * 8 + g;
                float v0 = wsh[buf][kb + tg][nB];
                float v1 = wsh[buf][kb + tg + 4][nB];
                bh[nt][0] = f2tf32(v0); bl[nt][0] = f2tf32(v0 - __uint_as_float(bh[nt][0]));
                bh[nt][1] = f2tf32(v1); bl[nt][1] = f2tf32(v1 - __uint_as_float(bh[nt][1]));
            }
#pragma unroll
            for (int mt = 0; mt < 2; mt++) {
#pragma unroll
                for (int nt = 0; nt < 8; nt++) {
                    float* d = acc[mt][nt];
#define MMA(A, B)                                                              \
    asm volatile(                                                              \
        "mma.sync.aligned.m16n8k8.row.col.f32.tf32.tf32.f32 "                  \
        "{%0,%1,%2,%3}, {%4,%5,%6,%7}, {%8,%9}, {%0,%1,%2,%3};"                \
        : "+f"(d[0]), "+f"(d[1]), "+f"(d[2]), "+f"(d[3])                       \
        : "r"((A)[0]), "r"((A)[1]), "r"((A)[2]), "r"((A)[3]),                  \
          "r"((B)[0]), "r"((B)[1]))
                    MMA(al[mt], bh[nt]);
                    MMA(ah[mt], bl[nt]);
                    MMA(ah[mt], bh[nt]);
#undef MMA
                }
            }
        }
        __syncthreads();
    }

    // epilogue
#pragma unroll
    for (int mt = 0; mt < 2; mt++) {
        int rowA = r0 + wr + mt * 16 + g;
        int rowB = rowA + 8;
#pragma unroll
        for (int nt = 0; nt < 8; nt++) {
            int colv = wc + nt * 8 + tg * 2;
            if (rowA < N_NODES)
                *(float2*)(g_y + (size_t)rowA * 128 + colv) =
                    make_float2(acc[mt][nt][0], acc[mt][nt][1]);
            if (rowB < N_NODES)
                *(float2*)(g_y + (size_t)rowB * 128 + colv) =
                    make_float2(acc[mt][nt][2], acc[mt][nt][3]);
        }
    }
}

// -------- dis = rsqrt(deg) (ordinal 4) --------
__global__ void k_rsqrt() {
    int i = blockIdx.x * blockDim.x + threadIdx.x;
    if (i < N_NODES) g_dis[i] = rsqrtf((float)g_deg[i]);
}

// -------- scan stage 1 (ordinal 5) --------
__global__ __launch_bounds__(1024) void k_scan_block() {
    __shared__ int sh[1024];
    int i = blockIdx.x * 1024 + threadIdx.x;
    sh[threadIdx.x] = (i < N_NODES) ? g_indeg[i] : 0;
    __syncthreads();
#pragma unroll
    for (int off = 512; off > 0; off >>= 1) {
        if (threadIdx.x < off) sh[threadIdx.x] += sh[threadIdx.x + off];
        __syncthreads();
    }
    if (threadIdx.x == 0) g_spine[blockIdx.x] = sh[0];
}

// -------- scan stage 2 (ordinal 6) --------
__global__ void k_scan_spine() {
    int acc = 0;
    for (int b = 0; b < NB; b++) { int v = g_spine[b]; g_spine[b] = acc; acc += v; }
}

// -------- scan stage 3 (ordinal 7) --------
__global__ __launch_bounds__(1024) void k_scan_final() {
    __shared__ int sh[1024];
    int i = blockIdx.x * 1024 + threadIdx.x;
    int v = (i < N_NODES) ? g_indeg[i] : 0;
    sh[threadIdx.x] = v;
    __syncthreads();
    for (int off = 1; off < 1024; off <<= 1) {
        int t = (threadIdx.x >= off) ? sh[threadIdx.x - off] : 0;
        __syncthreads();
        sh[threadIdx.x] += t;
        __syncthreads();
    }
    if (i < N_NODES) {
        int excl = sh[threadIdx.x] - v + g_spine[blockIdx.x];
        g_start[i] = excl;
        g_fill[i]  = excl;
    }
}

// -------- CSR fill (ordinal 8) --------
__global__ void k_fill(const int* __restrict__ row, const int* __restrict__ col) {
    int e = blockIdx.x * blockDim.x + threadIdx.x;
    int pos = atomicAdd(&g_fill[col[e]], 1);
    g_csr[pos] = row[e];
}

// -------- aggregate (ordinal 9) --------
__global__ __launch_bounds__(256) void k_agg(float* __restrict__ out) {
    const int warp = (blockIdx.x * 256 + threadIdx.x) >> 5;
    const int lane = threadIdx.x & 31;
    const float4* yy = (const float4*)g_y;

    const int c = warp;
    const float dc = g_dis[c];
    float4 acc = __ldg(yy + (size_t)c * 32 + lane);
    acc.x *= dc; acc.y *= dc; acc.z *= dc; acc.w *= dc;

    const int s = g_start[c];
    const int n = g_indeg[c];
    for (int k = 0; k < n; k++) {
        int src = __ldg(&g_csr[s + k]);
        float dr = __ldg(&g_dis[src]);
        float4 v = __ldg(yy + (size_t)src * 32 + lane);
        acc.x += dr * v.x; acc.y += dr * v.y;
        acc.z += dr * v.z; acc.w += dr * v.w;
    }
    acc.x *= dc; acc.y *= dc; acc.z *= dc; acc.w *= dc;
    ((float4*)out)[(size_t)c * 32 + lane] = acc;
}

extern "C" void kernel_launch(void* const* d_in, const int* in_sizes, int n_in,
                              void* d_out, int out_size) {
    const float* f     = (const float*)d_in[0];
    const int*   edges = (const int*)d_in[1];   // (2, E) int32
    const float* W     = (const float*)d_in[2];
    const float* b     = (const float*)d_in[3];
    float*       out   = (float*)d_out;

    const int* row = edges;
    const int* col = edges + E_EDGES;

    k_transpose_w<<<64, 256>>>(W);                         // 0
    k_init<<<(N_NODES + 255) / 256, 256>>>();              // 1
    k_count<<<E_EDGES / 256, 256>>>(row, col);             // 2
    k_gemm<<<(N_NODES + 63) / 64, 128>>>(f, b);            // 3  <- profiled slot
    k_rsqrt<<<(N_NODES + 255) / 256, 256>>>();             // 4
    k_scan_block<<<NB, 1024>>>();                          // 5
    k_scan_spine<<<1, 1>>>();                              // 6
    k_scan_final<<<NB, 1024>>>();                          // 7
    k_fill<<<E_EDGES / 256, 256>>>(row, col);              // 8
    k_agg<<<N_NODES / 8, 256>>>(out);                      // 9
}

// round 6
// speedup vs baseline: 1.3159x; 1.0771x over previous
#include <cuda_runtime.h>
#include <cstdint>
#include <cstddef>

#define N_NODES 100000
#define NHID    128
#define E_EDGES 1600000
#define NB      ((N_NODES + 1023) / 1024)   // 98 scan blocks
#define NG_GEMM ((N_NODES + 63) / 64)       // 1563 gemm blocks
#define NG_CNT  ((E_EDGES + 1023) / 1024)   // 1563 count blocks (128 thr x 8)

// -------- scratch (allocation-free: __device__ globals) --------
__device__ int   g_deg[N_NODES];
__device__ int   g_indeg[N_NODES];
__device__ float g_dis[N_NODES];
__device__ int   g_start[N_NODES];
__device__ int   g_fill[N_NODES];
__device__ int   g_csr[E_EDGES];
__device__ unsigned long long g_aggs[NB];        // decoupled-scan mailboxes
__device__ float g_y[(size_t)N_NODES * NHID];    // x = f @ W^T + b (unscaled)
__device__ float g_wt_hi[NHID * NHID];           // tf32-hi of W^T (k-major)
__device__ float g_wt_lo[NHID * NHID];           // residual lo part

__device__ __forceinline__ uint32_t f2tf32(float v) {
    uint32_t r;
    asm("cvt.rna.tf32.f32 %0, %1;" : "=r"(r) : "f"(v));
    return r;
}
__device__ __forceinline__ uint32_t smem_u32(const void* p) {
    uint32_t a;
    asm("{ .reg .u64 t; cvta.to.shared.u64 t, %1; cvt.u32.u64 %0, t; }"
        : "=r"(a) : "l"(p));
    return a;
}

// -------- prep: W transpose+split, deg/indeg init, mailbox clear (ordinal 0) ----
__global__ void k_prep(const float* __restrict__ W) {
    int idx = blockIdx.x * 256 + threadIdx.x;
    if (idx < 16384) {
        int k = idx >> 7, c = idx & 127;
        float v  = W[c * 128 + k];
        float hi = __uint_as_float(f2tf32(v));
        g_wt_hi[idx] = hi;
        g_wt_lo[idx] = __uint_as_float(f2tf32(v - hi));
    }
    int i = idx - 16384;
    if (i >= 0 && i < N_NODES) { g_deg[i] = 1; g_indeg[i] = 0; }
    int j = idx - 16384 - N_NODES;
    if (j >= 0 && j < NB) g_aggs[j] = 0ull;
}

// -------- fused GEMM (3xTF32 mma, cp.async 2-stage) + degree count (ordinal 1) --
// Even blocks: GEMM tile (64 rows x 128 cols). Odd blocks: count 1024 edges.
__global__ __launch_bounds__(128, 3) void k_gemm_count(const float* __restrict__ f,
                                                       const float* __restrict__ bias,
                                                       const int* __restrict__ row,
                                                       const int* __restrict__ col) {
    const int tid = threadIdx.x;

    if (blockIdx.x & 1) {   // ---- count role ----
        int base = (blockIdx.x >> 1) * 1024 + tid;
#pragma unroll
        for (int j = 0; j < 8; j++) {
            int e = base + j * 128;
            if (e < E_EDGES) {
                atomicAdd(&g_deg[row[e]], 1);
                atomicAdd(&g_indeg[col[e]], 1);
            }
        }
        return;
    }

    // ---- GEMM role ----
    __shared__ __align__(16) float fsh[2][64][20];    // raw f chunk, stride 20
    __shared__ __align__(16) float wshh[2][16][136];  // W hi chunk, stride 136
    __shared__ __align__(16) float wshl[2][16][136];  // W lo chunk

    const int warp = tid >> 5, lane = tid & 31;
    const int g    = lane >> 2, tg = lane & 3;
    const int wr   = (warp >> 1) * 32;
    const int wc   = (warp & 1) * 64;
    const int r0   = (blockIdx.x >> 1) * 64;

    float acc[2][8][4];
#pragma unroll
    for (int nt = 0; nt < 8; nt++) {
        float2 bv = __ldg((const float2*)(bias + wc + nt * 8) + tg);
#pragma unroll
        for (int mt = 0; mt < 2; mt++) {
            acc[mt][nt][0] = bv.x; acc[mt][nt][1] = bv.y;
            acc[mt][nt][2] = bv.x; acc[mt][nt][3] = bv.y;
        }
    }

    auto stage = [&](int buf, int k0) {
        // f chunk: 64 rows x 16 floats = 256 x 16B; clamp OOB rows (discarded)
#pragma unroll
        for (int j = 0; j < 2; j++) {
            int u = tid + 128 * j;
            int r = u >> 2, q = u & 3;
            int gr = r0 + r; if (gr >= N_NODES) gr = N_NODES - 1;
            uint32_t dst = smem_u32(&fsh[buf][r][q * 4]);
            const float* src = f + (size_t)gr * 128 + k0 + q * 4;
            asm volatile("cp.async.ca.shared.global [%0], [%1], 16;"
                         :: "r"(dst), "l"(src));
        }
        // W hi + lo chunks: 16 rows x 128 floats each = 512 x 16B each
#pragma unroll
        for (int j = 0; j < 4; j++) {
            int u = tid + 128 * j;
            int kk = u >> 5, q = u & 31;
            uint32_t dh = smem_u32(&wshh[buf][kk][q * 4]);
            const float* sh = g_wt_hi + (size_t)(k0 + kk) * 128 + q * 4;
            asm volatile("cp.async.ca.shared.global [%0], [%1], 16;"
                         :: "r"(dh), "l"(sh));
            uint32_t dl = smem_u32(&wshl[buf][kk][q * 4]);
            const float* sl = g_wt_lo + (size_t)(k0 + kk) * 128 + q * 4;
            asm volatile("cp.async.ca.shared.global [%0], [%1], 16;"
                         :: "r"(dl), "l"(sl));
        }
    };

    stage(0, 0);
    asm volatile("cp.async.commit_group;");

    for (int kc = 0; kc < 8; kc++) {
        asm volatile("cp.async.wait_group 0;");
        __syncthreads();
        if (kc + 1 < 8) {
            stage((kc + 1) & 1, (kc + 1) * 16);
            asm volatile("cp.async.commit_group;");
        }
        const int buf = kc & 1;

#pragma unroll
        for (int ks = 0; ks < 2; ks++) {
            const int kb = ks * 8;
            uint32_t ah[2][4], al[2][4];
#pragma unroll
            for (int mt = 0; mt < 2; mt++) {
                int rA = wr + mt * 16 + g;
                float v0 = fsh[buf][rA][kb + tg];
                float v1 = fsh[buf][rA + 8][kb + tg];
                float v2 = fsh[buf][rA][kb + tg + 4];
                float v3 = fsh[buf][rA + 8][kb + tg + 4];
                ah[mt][0] = f2tf32(v0); al[mt][0] = f2tf32(v0 - __uint_as_float(ah[mt][0]));
                ah[mt][1] = f2tf32(v1); al[mt][1] = f2tf32(v1 - __uint_as_float(ah[mt][1]));
                ah[mt][2] = f2tf32(v2); al[mt][2] = f2tf32(v2 - __uint_as_float(ah[mt][2]));
                ah[mt][3] = f2tf32(v3); al[mt][3] = f2tf32(v3 - __uint_as_float(ah[mt][3]));
            }
            uint32_t bh[8][2], bl[8][2];
#pragma unroll
            for (int nt = 0; nt < 8; nt++) {
                int nB = wc + nt * 8 + g;
                bh[nt][0] = __float_as_uint(wshh[buf][kb + tg][nB]);
                bh[nt][1] = __float_as_uint(wshh[buf][kb + tg + 4][nB]);
                bl[nt][0] = __float_as_uint(wshl[buf][kb + tg][nB]);
                bl[nt][1] = __float_as_uint(wshl[buf][kb + tg + 4][nB]);
            }
#pragma unroll
            for (int mt = 0; mt < 2; mt++) {
#pragma unroll
                for (int nt = 0; nt < 8; nt++) {
                    float* d = acc[mt][nt];
#define MMA(A, B)                                                              \
    asm volatile(                                                              \
        "mma.sync.aligned.m16n8k8.row.col.f32.tf32.tf32.f32 "                  \
        "{%0,%1,%2,%3}, {%4,%5,%6,%7}, {%8,%9}, {%0,%1,%2,%3};"                \
        : "+f"(d[0]), "+f"(d[1]), "+f"(d[2]), "+f"(d[3])                       \
        : "r"((A)[0]), "r"((A)[1]), "r"((A)[2]), "r"((A)[3]),                  \
          "r"((B)[0]), "r"((B)[1]))
                    MMA(al[mt], bh[nt]);
                    MMA(ah[mt], bl[nt]);
                    MMA(ah[mt], bh[nt]);
#undef MMA
                }
            }
        }
        __syncthreads();
    }

    // epilogue
#pragma unroll
    for (int mt = 0; mt < 2; mt++) {
        int rowA = r0 + wr + mt * 16 + g;
        int rowB = rowA + 8;
#pragma unroll
        for (int nt = 0; nt < 8; nt++) {
            int colv = wc + nt * 8 + tg * 2;
            if (rowA < N_NODES)
                *(float2*)(g_y + (size_t)rowA * 128 + colv) =
                    make_float2(acc[mt][nt][0], acc[mt][nt][1]);
            if (rowB < N_NODES)
                *(float2*)(g_y + (size_t)rowB * 128 + colv) =
                    make_float2(acc[mt][nt][2], acc[mt][nt][3]);
        }
    }
}

// -------- single-pass scan + rsqrt (ordinal 2) --------
// 98 blocks x 1024: all resident in wave 1; each block PUBLISHES its aggregate
// before POLLING lower blocks -> deadlock-free decoupled scan.
__global__ __launch_bounds__(1024) void k_scan() {
    __shared__ int sh[1024];
    __shared__ int pre[NB];
    __shared__ int s_off;
    const int b = blockIdx.x, tid = threadIdx.x;
    const int i = b * 1024 + tid;

    int v = 0;
    if (i < N_NODES) {
        v = g_indeg[i];
        g_dis[i] = rsqrtf((float)g_deg[i]);
    }
    sh[tid] = v;
    __syncthreads();
    for (int off = 1; off < 1024; off <<= 1) {           // inclusive scan
        int t = (tid >= off) ? sh[tid - off] : 0;
        __syncthreads();
        sh[tid] += t;
        __syncthreads();
    }
    if (tid == 0)
        atomicExch(&g_aggs[b], (1ull << 63) | (unsigned)sh[1023]);  // publish
    if (tid < b) {                                        // poll predecessors
        unsigned long long x;
        do { x = atomicAdd(&g_aggs[tid], 0ull); } while (!(x >> 63));
        pre[tid] = (int)(unsigned)x;
    }
    __syncthreads();
    if (tid == 0) {
        int a = 0;
        for (int j = 0; j < b; j++) a += pre[j];
        s_off = a;
    }
    __syncthreads();
    if (i < N_NODES) {
        int excl = sh[tid] - v + s_off;
        g_start[i] = excl;
        g_fill[i]  = excl;
    }
}

// -------- CSR fill (ordinal 3 -> profiled slot) --------
__global__ void k_fill(const int* __restrict__ row, const int* __restrict__ col) {
    int e = blockIdx.x * blockDim.x + threadIdx.x;   // exact grid: E/256
    int pos = atomicAdd(&g_fill[col[e]], 1);
    g_csr[pos] = row[e];
}

// -------- aggregate: out[c] = dis_c*(dis_c*x_c + sum_r dis_r*x_r) (ordinal 4) ----
__global__ __launch_bounds__(256) void k_agg(float* __restrict__ out) {
    const int warp = (blockIdx.x * 256 + threadIdx.x) >> 5;   // node id, exact grid
    const int lane = threadIdx.x & 31;
    const float4* yy = (const float4*)g_y;

    const int c = warp;
    const float dc = g_dis[c];
    float4 acc = __ldg(yy + (size_t)c * 32 + lane);
    acc.x *= dc; acc.y *= dc; acc.z *= dc; acc.w *= dc;

    const int s = g_start[c];
    const int n = g_indeg[c];
    for (int k = 0; k < n; k++) {
        int src = __ldg(&g_csr[s + k]);
        float dr = __ldg(&g_dis[src]);
        float4 v = __ldg(yy + (size_t)src * 32 + lane);
        acc.x += dr * v.x; acc.y += dr * v.y;
        acc.z += dr * v.z; acc.w += dr * v.w;
    }
    acc.x *= dc; acc.y *= dc; acc.z *= dc; acc.w *= dc;
    ((float4*)out)[(size_t)c * 32 + lane] = acc;
}

extern "C" void kernel_launch(void* const* d_in, const int* in_sizes, int n_in,
                              void* d_out, int out_size) {
    const float* f     = (const float*)d_in[0];
    const int*   edges = (const int*)d_in[1];   // (2, E) int32
    const float* W     = (const float*)d_in[2];
    const float* b     = (const float*)d_in[3];
    float*       out   = (float*)d_out;

    const int* row = edges;
    const int* col = edges + E_EDGES;

    k_prep<<<(16384 + N_NODES + NB + 255) / 256, 256>>>(W);        // 0
    k_gemm_count<<<NG_GEMM + NG_CNT, 128>>>(f, b, row, col);       // 1
    k_scan<<<NB, 1024>>>();                                        // 2
    k_fill<<<E_EDGES / 256, 256>>>(row, col);                      // 3
    k_agg<<<N_NODES / 8, 256>>>(out);                              // 4
}